// round 11
// baseline (speedup 1.0000x reference)
#include <cuda_runtime.h>
#include <math.h>
#include <stdint.h>

#define BB 256
#define TT 1000
#define NN 200
#define NII 7
#define HK 100          // K-half per CTA
#define RR 4            // batch rows per cluster

#define ALPHA_F 0.2f
#define OMA_F   0.8f
#define NSC_F   0.0948683292f   // 0.15*sqrt(2*0.2)

typedef unsigned long long u64;

__device__ __forceinline__ void ffma2(u64& acc, u64 w, u64 y) {
    asm("fma.rn.f32x2 %0, %1, %2, %0;" : "+l"(acc) : "l"(w), "l"(y));
}
__device__ __forceinline__ float hsum4(u64 a, u64 b) {
    u64 s; asm("add.rn.f32x2 %0, %1, %2;" : "=l"(s) : "l"(a), "l"(b));
    float2 f; asm("mov.b64 {%0, %1}, %2;" : "=f"(f.x), "=f"(f.y) : "l"(s));
    return f.x + f.y;
}
__device__ __forceinline__ uint32_t s2u(const void* p) {
    uint32_t a;
    asm("{ .reg .u64 t; cvta.to.shared.u64 t, %1; cvt.u32.u64 %0, t; }"
        : "=r"(a) : "l"(p));
    return a;
}
__device__ __forceinline__ uint32_t mapa_u32(uint32_t a, uint32_t r) {
    uint32_t o;
    asm("mapa.shared::cluster.u32 %0, %1, %2;" : "=r"(o) : "r"(a), "r"(r));
    return o;
}

__global__ void __launch_bounds__(256, 1) __cluster_dims__(2, 1, 1)
rnn_cluster_kernel(const float* __restrict__ y0,
                   const float* __restrict__ u_seq,
                   const float* __restrict__ noise,
                   const float* __restrict__ W_in_raw,
                   const float* __restrict__ W_rec,
                   const float* __restrict__ b_rec,
                   const float* __restrict__ w_out,
                   const float* __restrict__ b_out,
                   float* __restrict__ out)
{
    __shared__ __align__(16) float  y_s[2][RR][HK];     // own K-half of y
    __shared__ __align__(16) float4 pbuf[2][HK + 1];    // peer partials (4 rows each)
    __shared__ float u_s[2][RR][NII];
    __shared__ __align__(8) u64 mbar[2];

    const int tid = threadIdx.x;
    uint32_t rank; asm("mov.u32 %0, %%cluster_ctarank;" : "=r"(rank));
    const uint32_t peer = rank ^ 1u;
    const int rowbase = (int)(blockIdx.x >> 1) * RR;
    const int koff = (int)rank * HK;

    const bool is_dot  = (tid <= NN);                         // computes partials
    const bool is_epiN = (tid >= koff && tid < koff + HK);    // owns neuron tid
    const bool is_epiZ = (tid == NN && rank == 1);            // z readout
    const bool is_send = is_dot && !is_epiN && !is_epiZ;      // ships partials to peer
    const int  n_loc   = tid - koff;                          // local y index (epiN)
    const int  uq      = tid - 201;                           // u-loader lanes
    const bool is_u    = (uq >= 0 && uq < RR * NII);

    float* __restrict__ yseq = out;
    float* __restrict__ zseq = out + (size_t)BB * TT * NN;
    float* __restrict__ yfin = zseq + (size_t)BB * TT;

    // ---- mbarrier init (arrivals = peer's sender count) ----
    if (tid == 0) {
        uint32_t cnt = (rank == 0) ? HK : (HK + 1);   // CTA0 expects 100, CTA1 expects 101
        uint32_t m0 = s2u(&mbar[0]), m1 = s2u(&mbar[1]);
        asm volatile("mbarrier.init.shared.b64 [%0], %1;" :: "r"(m0), "r"(cnt));
        asm volatile("mbarrier.init.shared.b64 [%0], %1;" :: "r"(m1), "r"(cnt));
    }

    // ---- W K-half in registers (100 fp32 = 50 x b64) ----
    u64 w[HK / 2];
    if (is_dot) {
        const float* base = (tid == NN ? w_out : W_rec + (size_t)tid * NN) + koff;
        const u64* wp = reinterpret_cast<const u64*>(base);
        #pragma unroll
        for (int m = 0; m < HK / 2; ++m) w[m] = __ldg(&wp[m]);
    }

    float wia[NII];
    float brec = 0.f, bout = 0.f;
    float nz[RR] = {0.f, 0.f, 0.f, 0.f};
    float yv[RR] = {0.f, 0.f, 0.f, 0.f};
    if (is_epiN) {
        #pragma unroll
        for (int i = 0; i < NII; ++i) wia[i] = fabsf(W_in_raw[tid * NII + i]);
        brec = b_rec[tid];
        #pragma unroll
        for (int r = 0; r < RR; ++r) {
            float v = y0[(size_t)(rowbase + r) * NN + tid];
            y_s[0][r][n_loc] = v;
            yv[r] = v;
            nz[r] = noise[(size_t)(rowbase + r) * TT * NN + tid];
        }
    }
    if (tid == NN) bout = b_out[0];
    if (is_u) {
        int r = uq / NII, i = uq % NII;
        u_s[0][r][i] = u_seq[(size_t)(rowbase + r) * TT * NII + i];
    }

    // ---- remote addresses (static per thread) ----
    uint32_t rem_pb[2], rem_mb[2], my_mb[2];
    {
        int slot = tid - (int)peer * HK;                  // senders: 0..100
        int s = (slot >= 0 && slot <= HK) ? slot : 0;
        rem_pb[0] = mapa_u32(s2u(&pbuf[0][s]), peer);
        rem_pb[1] = mapa_u32(s2u(&pbuf[1][s]), peer);
        rem_mb[0] = mapa_u32(s2u(&mbar[0]), peer);
        rem_mb[1] = mapa_u32(s2u(&mbar[1]), peer);
        my_mb[0] = s2u(&mbar[0]);
        my_mb[1] = s2u(&mbar[1]);
    }

    __syncthreads();
    asm volatile("barrier.cluster.arrive.aligned;" ::: "memory");
    asm volatile("barrier.cluster.wait.aligned;" ::: "memory");

    int buf = 0;
    for (int t = 0; t <= TT; ++t) {                 // t==TT: z-only epilogue
        const uint32_t ph = (uint32_t)((t >> 1) & 1);

        // prefetch noise[t+1] / u[t+1]
        float nzn[RR] = {0.f, 0.f, 0.f, 0.f};
        if (is_epiN && (t + 1 < TT)) {
            #pragma unroll
            for (int r = 0; r < RR; ++r)
                nzn[r] = __ldcg(&noise[((size_t)(rowbase + r) * TT + (t + 1)) * NN + tid]);
        }
        float un = 0.f;
        if (is_u && (t + 1 < TT))
            un = __ldcg(&u_seq[((size_t)(rowbase + uq / NII) * TT + (t + 1)) * NII + (uq % NII)]);

        if (is_dot) {
            // ---- partial dot: 4 rows x K-half, 8 independent FFMA2 chains ----
            const ulonglong2* Y0 = reinterpret_cast<const ulonglong2*>(y_s[buf][0]);
            const ulonglong2* Y1 = reinterpret_cast<const ulonglong2*>(y_s[buf][1]);
            const ulonglong2* Y2 = reinterpret_cast<const ulonglong2*>(y_s[buf][2]);
            const ulonglong2* Y3 = reinterpret_cast<const ulonglong2*>(y_s[buf][3]);
            u64 a0 = 0, b0 = 0, a1 = 0, b1 = 0, a2 = 0, b2 = 0, a3 = 0, b3 = 0;
            #pragma unroll
            for (int m = 0; m < HK / 4; ++m) {
                ulonglong2 q0 = Y0[m], q1 = Y1[m], q2 = Y2[m], q3 = Y3[m];
                ffma2(a0, w[2 * m], q0.x); ffma2(b0, w[2 * m + 1], q0.y);
                ffma2(a1, w[2 * m], q1.x); ffma2(b1, w[2 * m + 1], q1.y);
                ffma2(a2, w[2 * m], q2.x); ffma2(b2, w[2 * m + 1], q2.y);
                ffma2(a3, w[2 * m], q3.x); ffma2(b3, w[2 * m + 1], q3.y);
            }
            float p0 = hsum4(a0, b0), p1 = hsum4(a1, b1);
            float p2 = hsum4(a2, b2), p3 = hsum4(a3, b3);

            // ---- senders FIRST (sequential ifs: no divergent-spin deadlock) ----
            if (is_send) {
                asm volatile("st.shared::cluster.v4.f32 [%0], {%1, %2, %3, %4};"
                             :: "r"(rem_pb[buf]), "f"(p0), "f"(p1), "f"(p2), "f"(p3)
                             : "memory");
                asm volatile("mbarrier.arrive.release.cluster.shared::cluster.b64 _, [%0];"
                             :: "r"(rem_mb[buf]) : "memory");
            }
            if (!is_send && (t < TT || is_epiZ)) {
                asm volatile("{\n\t.reg .pred P;\nWL%=:\n\t"
                             "mbarrier.try_wait.parity.acquire.cluster.shared::cta.b64 P, [%0], %1;\n\t"
                             "@P bra WD%=;\n\tbra WL%=;\nWD%=:\n}"
                             :: "r"(my_mb[buf]), "r"(ph) : "memory");
                if (is_epiZ) {
                    float4 rp = pbuf[buf][HK];
                    if (t >= 1) {
                        zseq[(size_t)(rowbase + 0) * TT + (t - 1)] = 1.f / (1.f + expf(-(p0 + rp.x + bout)));
                        zseq[(size_t)(rowbase + 1) * TT + (t - 1)] = 1.f / (1.f + expf(-(p1 + rp.y + bout)));
                        zseq[(size_t)(rowbase + 2) * TT + (t - 1)] = 1.f / (1.f + expf(-(p2 + rp.z + bout)));
                        zseq[(size_t)(rowbase + 3) * TT + (t - 1)] = 1.f / (1.f + expf(-(p3 + rp.w + bout)));
                    }
                } else {   // is_epiN, t < TT
                    float4 rp = pbuf[buf][n_loc];
                    float pr[RR] = {p0 + rp.x, p1 + rp.y, p2 + rp.z, p3 + rp.w};
                    #pragma unroll
                    for (int r = 0; r < RR; ++r) {
                        float dr = brec;
                        #pragma unroll
                        for (int i = 0; i < NII; ++i)
                            dr = fmaf(wia[i], u_s[buf][r][i], dr);
                        float rl = fmaxf(pr[r] + dr, 0.f);
                        float yn = fmaf(OMA_F, yv[r], fmaf(ALPHA_F, rl, NSC_F * nz[r]));
                        y_s[buf ^ 1][r][n_loc] = yn;
                        __stcs(&yseq[((size_t)(rowbase + r) * TT + t) * NN + tid], yn);
                        yv[r] = yn;
                        nz[r] = nzn[r];
                    }
                }
            }
        }
        if (is_u && (t + 1 < TT))
            u_s[buf ^ 1][uq / NII][uq % NII] = un;
        __syncthreads();
        buf ^= 1;
    }

    // ---- EXIT ORDERING FIX: no CTA may exit while peer remote stores/arrives
    // targeting its SMEM can still be in flight (this was R10's fault). ----
    asm volatile("barrier.cluster.arrive.aligned;" ::: "memory");
    asm volatile("barrier.cluster.wait.aligned;" ::: "memory");

    // ---- y_final = y[T-1] ----
    if (is_epiN) {
        #pragma unroll
        for (int r = 0; r < RR; ++r)
            yfin[(size_t)(rowbase + r) * NN + tid] = yv[r];
    }
}

extern "C" void kernel_launch(void* const* d_in, const int* in_sizes, int n_in,
                              void* d_out, int out_size) {
    const float* y0       = (const float*)d_in[0];
    const float* u_seq    = (const float*)d_in[1];
    const float* noise    = (const float*)d_in[2];
    const float* W_in_raw = (const float*)d_in[3];
    const float* W_rec    = (const float*)d_in[4];
    const float* b_rec    = (const float*)d_in[5];
    const float* w_out    = (const float*)d_in[6];
    const float* b_out    = (const float*)d_in[7];
    float* out = (float*)d_out;

    rnn_cluster_kernel<<<BB / 2, 256>>>(y0, u_seq, noise, W_in_raw, W_rec,
                                        b_rec, w_out, b_out, out);
}

// round 12
// speedup vs baseline: 1.3988x; 1.3988x over previous
#include <cuda_runtime.h>
#include <math.h>

// Problem constants
#define BB 256
#define TT 1000
#define NN 200
#define NII 7

#define ALPHA_F 0.2f
#define OMA_F   0.8f
#define NSC_F   0.0948683292f   // 0.15*sqrt(2*0.2)

typedef unsigned long long u64;

// packed fp32x2 FMA, operands pre-packed in b64 (no operand MOVs)
__device__ __forceinline__ void ffma2(u64& acc, u64 w, u64 y) {
    asm("fma.rn.f32x2 %0, %1, %2, %0;" : "+l"(acc) : "l"(w), "l"(y));
}
__device__ __forceinline__ float hsum4(u64 a, u64 b) {
    u64 s; asm("add.rn.f32x2 %0, %1, %2;" : "=l"(s) : "l"(a), "l"(b));
    float2 f; asm("mov.b64 {%0, %1}, %2;" : "=f"(f.x), "=f"(f.y) : "l"(s));
    return f.x + f.y;
}

__global__ void __launch_bounds__(256, 1)
rnn_persistent_kernel(const float* __restrict__ y0,
                      const float* __restrict__ u_seq,
                      const float* __restrict__ noise,
                      const float* __restrict__ W_in_raw,
                      const float* __restrict__ W_rec,
                      const float* __restrict__ b_rec,
                      const float* __restrict__ w_out,
                      const float* __restrict__ b_out,
                      float* __restrict__ out)
{
    __shared__ __align__(16) float y_s[2][2][NN];   // [buf][row][neuron]
    __shared__ __align__(16) float nsm[2][2][NN];   // noise double buffer (DMA warp)
    __shared__ float u_s[2][2][NII];                // [buf][row][input]
    __shared__ __align__(16) float wia_s[NN * 8];   // [n*8+i]: i<7 |W_in|, i=7 b_rec

    const int tid  = threadIdx.x;
    const int n    = tid;                // 0..199 neurons; 200 z; 201..223 idle; 224..255 DMA
    const int lane = tid & 31;
    const bool is_dma    = (tid >= 224);            // warp 7, warp-aligned
    const bool is_neuron = (n <  NN);
    const bool is_z      = (n == NN);
    const bool active    = (n <= NN);
    const int  b0 = blockIdx.x * 2;
    const int  b1 = b0 + 1;

    float* __restrict__ yseq = out;
    float* __restrict__ zseq = out + (size_t)BB * TT * NN;
    float* __restrict__ yfin = zseq + (size_t)BB * TT;

    // ---- full W row in registers (200 fp32 = 100 x b64) ----
    u64 w[NN / 2];
    if (active) {
        const float* base = is_z ? w_out : (W_rec + (size_t)n * NN);
        const u64* wp = reinterpret_cast<const u64*>(base);
        #pragma unroll
        for (int m = 0; m < NN / 2; ++m) w[m] = __ldg(&wp[m]);
    }

    // |W_in| and b_rec into SMEM (frees 8 regs on neuron threads)
    for (int idx = tid; idx < NN * NII; idx += 256) {
        int nn = idx / NII, i = idx % NII;
        wia_s[nn * 8 + i] = fabsf(W_in_raw[idx]);
    }
    if (tid < NN) wia_s[tid * 8 + 7] = b_rec[tid];

    float bout = 0.f, yold0 = 0.f, yold1 = 0.f;
    if (is_neuron) {
        yold0 = y0[(size_t)b0 * NN + n];
        yold1 = y0[(size_t)b1 * NN + n];
        y_s[0][0][n] = yold0;
        y_s[0][1][n] = yold1;
    }
    if (is_z) bout = b_out[0];

    // DMA warp primes noise[0] and u[0]
    if (is_dma) {
        #pragma unroll
        for (int q = lane; q < 100; q += 32) {
            int row = q / 50, j = q % 50;
            const float4* src = reinterpret_cast<const float4*>(
                noise + (size_t)(b0 + row) * TT * NN) + j;
            reinterpret_cast<float4*>(nsm[0][row])[j] = __ldg(src);
        }
        if (lane < 2 * NII) {
            int bl = lane / NII, i = lane % NII;
            u_s[0][bl][i] = __ldg(&u_seq[(size_t)(b0 + bl) * TT * NII + i]);
        }
    }
    __syncthreads();

    // incremental y_seq pointers (neurons only)
    float* yp0 = yseq + (size_t)b0 * TT * NN + (is_neuron ? n : 0);
    float* yp1 = yseq + (size_t)b1 * TT * NN + (is_neuron ? n : 0);

    int buf = 0;
    for (int t = 0; t < TT; ++t) {
        if (is_dma) {
            // ======== DMA warp: prefetch noise[t+1], u[t+1] into buf^1 ========
            if (t + 1 < TT) {
                #pragma unroll
                for (int q = lane; q < 100; q += 32) {
                    int row = q / 50, j = q % 50;
                    const float4* src = reinterpret_cast<const float4*>(
                        noise + ((size_t)(b0 + row) * TT + (t + 1)) * NN) + j;
                    reinterpret_cast<float4*>(nsm[buf ^ 1][row])[j] = __ldcs(src);
                }
                if (lane < 2 * NII) {
                    int bl = lane / NII, i = lane % NII;
                    u_s[buf ^ 1][bl][i] =
                        __ldcs(&u_seq[((size_t)(b0 + bl) * TT + (t + 1)) * NII + i]);
                }
            }
        } else if (active) {
            // ======== compute: dot with explicit 2-deep LDS pipeline ========
            const ulonglong2* Y0 = reinterpret_cast<const ulonglong2*>(y_s[buf][0]);
            const ulonglong2* Y1 = reinterpret_cast<const ulonglong2*>(y_s[buf][1]);
            u64 c0a = 0ull, c0b = 0ull, c1a = 0ull, c1b = 0ull;

            ulonglong2 p0 = Y0[0], q0 = Y1[0];
            ulonglong2 p1 = Y0[1], q1 = Y1[1];
            #pragma unroll
            for (int m = 0; m < 48; m += 2) {
                ulonglong2 pa = Y0[m + 2], qa = Y1[m + 2];
                ffma2(c0a, w[2 * m],     p0.x); ffma2(c0b, w[2 * m + 1], p0.y);
                ffma2(c1a, w[2 * m],     q0.x); ffma2(c1b, w[2 * m + 1], q0.y);
                ulonglong2 pb = Y0[m + 3], qb = Y1[m + 3];
                ffma2(c0a, w[2 * m + 2], p1.x); ffma2(c0b, w[2 * m + 3], p1.y);
                ffma2(c1a, w[2 * m + 2], q1.x); ffma2(c1b, w[2 * m + 3], q1.y);
                p0 = pa; q0 = qa; p1 = pb; q1 = qb;
            }
            ffma2(c0a, w[96], p0.x); ffma2(c0b, w[97], p0.y);
            ffma2(c1a, w[96], q0.x); ffma2(c1b, w[97], q0.y);
            ffma2(c0a, w[98], p1.x); ffma2(c0b, w[99], p1.y);
            ffma2(c1a, w[98], q1.x); ffma2(c1b, w[99], q1.y);

            float pre0 = hsum4(c0a, c0b);
            float pre1 = hsum4(c1a, c1b);

            if (is_neuron) {
                // wia + brec from SMEM (2 x LDS.128)
                float4 wa = *reinterpret_cast<const float4*>(&wia_s[n * 8]);
                float4 wb = *reinterpret_cast<const float4*>(&wia_s[n * 8 + 4]);
                float dr0 = wb.w, dr1 = wb.w;                 // b_rec
                dr0 = fmaf(wa.x, u_s[buf][0][0], dr0);
                dr1 = fmaf(wa.x, u_s[buf][1][0], dr1);
                dr0 = fmaf(wa.y, u_s[buf][0][1], dr0);
                dr1 = fmaf(wa.y, u_s[buf][1][1], dr1);
                dr0 = fmaf(wa.z, u_s[buf][0][2], dr0);
                dr1 = fmaf(wa.z, u_s[buf][1][2], dr1);
                dr0 = fmaf(wa.w, u_s[buf][0][3], dr0);
                dr1 = fmaf(wa.w, u_s[buf][1][3], dr1);
                dr0 = fmaf(wb.x, u_s[buf][0][4], dr0);
                dr1 = fmaf(wb.x, u_s[buf][1][4], dr1);
                dr0 = fmaf(wb.y, u_s[buf][0][5], dr0);
                dr1 = fmaf(wb.y, u_s[buf][1][5], dr1);
                dr0 = fmaf(wb.z, u_s[buf][0][6], dr0);
                dr1 = fmaf(wb.z, u_s[buf][1][6], dr1);

                float nz0 = nsm[buf][0][n];
                float nz1 = nsm[buf][1][n];
                float r0 = fmaxf(pre0 + dr0, 0.f);
                float r1 = fmaxf(pre1 + dr1, 0.f);
                float yn0 = fmaf(OMA_F, yold0, fmaf(ALPHA_F, r0, NSC_F * nz0));
                float yn1 = fmaf(OMA_F, yold1, fmaf(ALPHA_F, r1, NSC_F * nz1));
                y_s[buf ^ 1][0][n] = yn0;
                y_s[buf ^ 1][1][n] = yn1;
                __stcs(yp0, yn0);
                __stcs(yp1, yn1);
                yp0 += NN; yp1 += NN;
                yold0 = yn0; yold1 = yn1;
            } else if (t >= 1) {
                // z thread's dot was over y_{t-1}
                zseq[(size_t)b0 * TT + (t - 1)] = 1.f / (1.f + expf(-(pre0 + bout)));
                zseq[(size_t)b1 * TT + (t - 1)] = 1.f / (1.f + expf(-(pre1 + bout)));
            }
        }
        __syncthreads();
        buf ^= 1;
    }

    // ---- tails ----
    if (is_neuron) {
        yfin[(size_t)b0 * NN + n] = yold0;
        yfin[(size_t)b1 * NN + n] = yold1;
    }
    if (is_z) {
        const ulonglong2* Y0 = reinterpret_cast<const ulonglong2*>(y_s[buf][0]);
        const ulonglong2* Y1 = reinterpret_cast<const ulonglong2*>(y_s[buf][1]);
        u64 c0a = 0ull, c0b = 0ull, c1a = 0ull, c1b = 0ull;
        #pragma unroll
        for (int m = 0; m < NN / 4; ++m) {
            ulonglong2 p = Y0[m];
            ulonglong2 q = Y1[m];
            ffma2(c0a, w[2 * m],     p.x);
            ffma2(c0b, w[2 * m + 1], p.y);
            ffma2(c1a, w[2 * m],     q.x);
            ffma2(c1b, w[2 * m + 1], q.y);
        }
        float pre0 = hsum4(c0a, c0b);
        float pre1 = hsum4(c1a, c1b);
        zseq[(size_t)b0 * TT + (TT - 1)] = 1.f / (1.f + expf(-(pre0 + bout)));
        zseq[(size_t)b1 * TT + (TT - 1)] = 1.f / (1.f + expf(-(pre1 + bout)));
    }
}

extern "C" void kernel_launch(void* const* d_in, const int* in_sizes, int n_in,
                              void* d_out, int out_size) {
    const float* y0       = (const float*)d_in[0];
    const float* u_seq    = (const float*)d_in[1];
    const float* noise    = (const float*)d_in[2];
    const float* W_in_raw = (const float*)d_in[3];
    const float* W_rec    = (const float*)d_in[4];
    const float* b_rec    = (const float*)d_in[5];
    const float* w_out    = (const float*)d_in[6];
    const float* b_out    = (const float*)d_in[7];
    float* out = (float*)d_out;

    rnn_persistent_kernel<<<BB / 2, 256>>>(y0, u_seq, noise, W_in_raw, W_rec,
                                           b_rec, w_out, b_out, out);
}